// round 6
// baseline (speedup 1.0000x reference)
#include <cuda_runtime.h>
#include <cstdint>

// Problem constants (fixed by the dataset)
#define B_   16
#define S_   2048
#define D_   1024
#define P_   8192
#define R_   16

#define LCH  32               // rows per chunk == MAX_SPAN (load-bearing!)
#define NCH  (S_ / LCH)       // 64 chunks
#define OUTW (2 * D_ + R_)    // 2064 floats per output row

#define PPB  4                // pairs per block (128 threads each)

// arr[b][s][d]: inclusive prefix of tok within the chunk containing s (only flagged rows valid)
__device__ float g_arr[(size_t)B_ * S_ * D_];            // ~134 MB address space, ~83 MB touched
__device__ float g_part[(size_t)B_ * NCH * D_];          // chunk totals (4 MB, L2-resident)
__device__ int   g_flag[(B_ * S_) / 4];                  // packed byte flags (8K ints)

// ---------------------------------------------------------------------------
__global__ void k_init_flags() {
    int i = blockIdx.x * blockDim.x + threadIdx.x;
    if (i < (B_ * S_) / 4) g_flag[i] = 0;
}

// Mark rows of arr that k_pairs will read: for endpoint e>0, row (e-1) of batch b.
__global__ void k_mark(const int* __restrict__ batch_idx,
                       const int* __restrict__ e1s, const int* __restrict__ e1e,
                       const int* __restrict__ e2s, const int* __restrict__ e2e) {
    int i = blockIdx.x * blockDim.x + threadIdx.x;      // [0, 4P)
    if (i >= 4 * P_) return;
    int p = i & (P_ - 1);
    int which = i >> 13;                                 // P = 8192 = 2^13
    int e;
    switch (which) {
        case 0: e = e1s[p]; break;
        case 1: e = e1e[p]; break;
        case 2: e = e2s[p]; break;
        default: e = e2e[p]; break;
    }
    if (e > 0) ((unsigned char*)g_flag)[batch_idx[p] * S_ + (e - 1)] = 1;
}

// ---------------------------------------------------------------------------
// Single tok pass: per (b, chunk, d4) running prefix; write only flagged rows;
// emit chunk total unconditionally. tok read ONCE -> streaming loads (.cs)
// so arr/part writes stay L2-resident for k_pairs.
__global__ void k_local_prefix(const float* __restrict__ tok) {
    __shared__ unsigned char sflag[LCH];
    int idx = blockIdx.x * blockDim.x + threadIdx.x;
    int d4   = idx & (D_ / 4 - 1);
    int rest = idx >> 8;                                  // D/4 = 256
    int ch   = rest & (NCH - 1);
    int b    = rest >> 6;                                 // NCH = 64

    if (threadIdx.x < LCH)
        sflag[threadIdx.x] = ((const unsigned char*)g_flag)[b * S_ + ch * LCH + threadIdx.x];
    __syncthreads();

    const float4* t  = (const float4*)(tok   + ((size_t)b * S_ + (size_t)ch * LCH) * D_) + d4;
    float4*       ar = (float4*)      (g_arr + ((size_t)b * S_ + (size_t)ch * LCH) * D_) + d4;

    float4 run = make_float4(0.f, 0.f, 0.f, 0.f);
#pragma unroll
    for (int i = 0; i < LCH; ++i) {
        float4 v = __ldcs(t + (size_t)i * (D_ / 4));     // streaming read
        run.x += v.x; run.y += v.y; run.z += v.z; run.w += v.w;
        if (sflag[i]) ar[(size_t)i * (D_ / 4)] = run;    // keep in L2
    }
    ((float4*)(g_part + ((size_t)b * NCH + ch) * D_))[d4] = run;
}

// ---------------------------------------------------------------------------
// k_pairs: 128 threads per pair, each thread owns float4 lanes t and t+128.
// All independent loads issued up-front for max memory-level parallelism.
// Span algebra (span <= LCH => endpoints in same or adjacent chunks):
//   s == 0          : num = arr[f-1]
//   same chunk      : num = arr[f-1] - arr[s-1]
//   adjacent chunks : num = arr[f-1] - arr[s-1] + part[chunk(s-1)]
__device__ __forceinline__ float4 f4_sub(float4 a, float4 b) {
    return make_float4(a.x - b.x, a.y - b.y, a.z - b.z, a.w - b.w);
}
__device__ __forceinline__ float4 f4_add(float4 a, float4 b) {
    return make_float4(a.x + b.x, a.y + b.y, a.z + b.z, a.w + b.w);
}
__device__ __forceinline__ float4 f4_scale(float4 a, float s) {
    return make_float4(a.x * s, a.y * s, a.z * s, a.w * s);
}

__global__ void __launch_bounds__(128 * PPB)
k_pairs(const int* __restrict__ batch_idx,
        const int* __restrict__ e1s, const int* __restrict__ e1e,
        const int* __restrict__ e2s, const int* __restrict__ e2e,
        const int* __restrict__ rel_idx,
        const float* __restrict__ rel_table,
        float* __restrict__ out) {
    int p = blockIdx.x * PPB + (threadIdx.x >> 7);
    int t = threadIdx.x & 127;           // lane: float4 indices t and t+128

    int b  = __ldg(batch_idx + p);
    int s1 = __ldg(e1s + p), f1 = __ldg(e1e + p);
    int s2 = __ldg(e2s + p), f2 = __ldg(e2e + p);

    const float4* arr_b  = (const float4*)(g_arr  + (size_t)b * S_ * D_);
    const float4* part_b = (const float4*)(g_part + (size_t)b * NCH * D_);

    size_t rf1 = (size_t)(f1 - 1) * (D_ / 4);
    size_t rf2 = (size_t)(f2 - 1) * (D_ / 4);

    // ---- issue every independent load before any compute/store ----
    float4 h1a = arr_b[rf1 + t];
    float4 h1b = arr_b[rf1 + t + 128];
    float4 h2a = arr_b[rf2 + t];
    float4 h2b = arr_b[rf2 + t + 128];

    float4 n1a = h1a, n1b = h1b, n2a = h2a, n2b = h2b;

    if (s1 > 0) {                               // pair-uniform branch
        size_t rs1 = (size_t)(s1 - 1) * (D_ / 4);
        float4 l1a = arr_b[rs1 + t];
        float4 l1b = arr_b[rs1 + t + 128];
        int cbs = (s1 - 1) >> 5, cbf = (f1 - 1) >> 5;
        if (cbf != cbs) {
            size_t rp = (size_t)cbs * (D_ / 4);
            float4 pa = part_b[rp + t];
            float4 pb = part_b[rp + t + 128];
            n1a = f4_add(f4_sub(h1a, l1a), pa);
            n1b = f4_add(f4_sub(h1b, l1b), pb);
        } else {
            n1a = f4_sub(h1a, l1a);
            n1b = f4_sub(h1b, l1b);
        }
    }
    if (s2 > 0) {
        size_t rs2 = (size_t)(s2 - 1) * (D_ / 4);
        float4 l2a = arr_b[rs2 + t];
        float4 l2b = arr_b[rs2 + t + 128];
        int cbs = (s2 - 1) >> 5, cbf = (f2 - 1) >> 5;
        if (cbf != cbs) {
            size_t rp = (size_t)cbs * (D_ / 4);
            float4 pa = part_b[rp + t];
            float4 pb = part_b[rp + t + 128];
            n2a = f4_add(f4_sub(h2a, l2a), pa);
            n2b = f4_add(f4_sub(h2b, l2b), pb);
        } else {
            n2a = f4_sub(h2a, l2a);
            n2b = f4_sub(h2b, l2b);
        }
    }

    float inv1 = 1.0f / (float)(f1 - s1);
    float inv2 = 1.0f / (float)(f2 - s2);

    float4* orow = (float4*)(out + (size_t)p * OUTW);
    __stcs(orow + t,             f4_scale(n1a, inv1));
    __stcs(orow + t + 128,       f4_scale(n1b, inv1));
    __stcs(orow + 256 + t,       f4_scale(n2a, inv2));
    __stcs(orow + 256 + t + 128, f4_scale(n2b, inv2));

    if (t < R_) {
        int ri = __ldg(rel_idx + p);
        __stcs(out + (size_t)p * OUTW + 2 * D_ + t,
               __ldg(rel_table + (size_t)ri * R_ + t));
    }
}

// ---------------------------------------------------------------------------
extern "C" void kernel_launch(void* const* d_in, const int* in_sizes, int n_in,
                              void* d_out, int out_size) {
    const float* tok       = (const float*)d_in[0];
    const int*   batch_idx = (const int*)d_in[1];
    const int*   e1s       = (const int*)d_in[2];
    const int*   e1e       = (const int*)d_in[3];
    const int*   e2s       = (const int*)d_in[4];
    const int*   e2e       = (const int*)d_in[5];
    const int*   rel_idx   = (const int*)d_in[6];
    const float* rel_table = (const float*)d_in[7];
    float* out = (float*)d_out;

    (void)in_sizes; (void)n_in; (void)out_size;

    k_init_flags<<<(B_ * S_ / 4 + 255) / 256, 256>>>();
    k_mark<<<(4 * P_) / 256, 256>>>(batch_idx, e1s, e1e, e2s, e2e);
    k_local_prefix<<<B_ * NCH * (D_ / 4) / 256, 256>>>(tok);
    k_pairs<<<P_ / PPB, 128 * PPB>>>(batch_idx, e1s, e1e, e2s, e2e,
                                     rel_idx, rel_table, out);
}